// round 14
// baseline (speedup 1.0000x reference)
#include <cuda_runtime.h>
#include <cuda_fp16.h>
#include <cstdint>
#include <math_constants.h>

#define BATCH 4
#define SEQ   2048
#define DM    1024
#define MROWS (BATCH * SEQ)
#define SCALE (1.0f / 32.0f)

// GEMM tiling (fp16 operands, fp32 accum)
#define BM 128
#define BN 128
#define BK 64
#define S_H 80                        // row stride in fp16 (64 + 16 pad)
#define TILE_H (BM * S_H)             // 10240 halfs per tile (20480 B)
#define STG_H  (2 * TILE_H)           // A+B per stage
#define SMEM_BYTES (2 * STG_H * 2)    // 81920 B (2 stages)

// Scratch (__device__ globals; allocation-free rule)
__device__ __half g_xh [(size_t)MROWS * DM];         // x   (fp16)
__device__ __half g_wh [(size_t)3 * DM * DM];        // slot0: Wq, slot1: Wk (row-major);
                                                     // slot2: Wv^T
__device__ __half g_mth[(size_t)DM * DM];            // (Wq Wk^T / 32)^T  (fp16)
__device__ __half g_th [(size_t)MROWS * DM];         // T = x (Wq Wk^T / 32)  (fp16)
__device__ __half g_vth[(size_t)MROWS * DM];         // V^T per batch [b][d][key]
__device__ __half g_ph [(size_t)BATCH * SEQ * SEQ];  // scores -> probs (fp16, in place)

// Dataflow counters (reset by prepass each run)
__device__ int g_mcnt;
__device__ int g_tcnt[64];
__device__ int g_vcnt[32];
__device__ int g_scnt[64];
__device__ int g_smcnt[64];

// ---------------------------------------------------------------------------
__device__ __forceinline__ void cp16(uint32_t dst, const void* src) {
    asm volatile("cp.async.cg.shared.global [%0], [%1], 16;"
                 :: "r"(dst), "l"(src) : "memory");
}

__device__ __forceinline__ void mma16(float* c, const uint32_t* a, const uint32_t* b) {
    asm volatile(
        "mma.sync.aligned.m16n8k16.row.col.f32.f16.f16.f32 "
        "{%0,%1,%2,%3}, {%4,%5,%6,%7}, {%8,%9}, {%0,%1,%2,%3};"
        : "+f"(c[0]), "+f"(c[1]), "+f"(c[2]), "+f"(c[3])
        : "r"(a[0]), "r"(a[1]), "r"(a[2]), "r"(a[3]), "r"(b[0]), "r"(b[1]));
}

// Issue cp.async for a 128x64-fp16 K-major tile into padded SMEM.
__device__ __forceinline__ void load_tile(uint32_t smbase_b, const __half* __restrict__ src,
                                          long ld, int tid) {
    #pragma unroll
    for (int i = 0; i < 4; ++i) {
        int idx = i * 256 + tid;
        int row = idx >> 3, c8 = idx & 7;
        cp16(smbase_b + (uint32_t)(row * (S_H * 2) + c8 * 16),
             src + (size_t)row * ld + c8 * 8);
    }
}

// Load one k16-step of fragments via LDS.64, immediate offsets.
// k-permutation: quad-lane lc reads physical cols 4lc..4lc+3 as logical
// {2lc, 2lc+1, 2lc+8, 2lc+9}; A and B agree, so the k-sum is unchanged.
__device__ __forceinline__ void load_frags(const __half* __restrict__ aP,
                                           const __half* __restrict__ bP,
                                           int ks, uint32_t* a, uint32_t* b) {
    const int k = ks * 16;
    const uint2 u0 = *(const uint2*)(aP + k);               // t=0 row lr
    const uint2 u1 = *(const uint2*)(aP + 8 * S_H + k);     // t=0 row lr+8
    const uint2 u2 = *(const uint2*)(aP + 16 * S_H + k);    // t=1 row lr
    const uint2 u3 = *(const uint2*)(aP + 24 * S_H + k);    // t=1 row lr+8
    a[0] = u0.x; a[1] = u1.x; a[2] = u0.y; a[3] = u1.y;
    a[4] = u2.x; a[5] = u3.x; a[6] = u2.y; a[7] = u3.y;
    #pragma unroll
    for (int u = 0; u < 8; ++u) {
        const uint2 w = *(const uint2*)(bP + u * 8 * S_H + k);
        b[u * 2 + 0] = w.x;
        b[u * 2 + 1] = w.y;
    }
}

// ---------------------------------------------------------------------------
// NT GEMM mainloop: C(128x128,f32) += A(128xK,f16) * B(128xK,f16)^T.
// 2-stage cp.async pipeline, 1 barrier/chunk, k16-level register pipelining.
// ---------------------------------------------------------------------------
__device__ __forceinline__ void gemm_h(__half* sm,
                                       const __half* __restrict__ A, long lda,
                                       const __half* __restrict__ B, long ldb,
                                       int nchunks, float c[2][8][4]) {
    const int tid = threadIdx.x, wid = tid >> 5, lane = tid & 31;
    const int warpM = wid & 3, warpN = wid >> 2;
    const int lr = lane >> 2, lc = lane & 3;
    const uint32_t smu = (uint32_t)__cvta_generic_to_shared(sm);

    const __half* aP0 = sm + (warpM * 32 + lr) * S_H + 4 * lc;
    const __half* bP0 = sm + TILE_H + (warpN * 64 + lr) * S_H + 4 * lc;
    const __half* aP1 = aP0 + STG_H;
    const __half* bP1 = bP0 + STG_H;

    load_tile(smu, A, lda, tid);
    load_tile(smu + TILE_H * 2, B, ldb, tid);
    asm volatile("cp.async.commit_group;" ::: "memory");

    for (int i = 0; i < nchunks; ++i) {
        asm volatile("cp.async.wait_group 0;" ::: "memory");
        __syncthreads();

        const __half* aP = (i & 1) ? aP1 : aP0;
        const __half* bP = (i & 1) ? bP1 : bP0;

        // Critical path first: ks=0 fragments.
        uint32_t aA[8], bA[16], aB[8], bB[16];
        load_frags(aP, bP, 0, aA, bA);

        // Prefetch chunk i+1 (overlaps with MMAs below).
        if (i + 1 < nchunks) {
            const uint32_t s = (uint32_t)((i + 1) & 1) * STG_H * 2;
            load_tile(smu + s, A + (size_t)(i + 1) * BK, lda, tid);
            load_tile(smu + s + TILE_H * 2, B + (size_t)(i + 1) * BK, ldb, tid);
            asm volatile("cp.async.commit_group;" ::: "memory");
        }

        #pragma unroll
        for (int ks = 0; ks < 4; ++ks) {
            if (ks < 3)
                load_frags(aP, bP, ks + 1,
                           (ks & 1) ? aA : aB, (ks & 1) ? bA : bB);
            const uint32_t* a = (ks & 1) ? aB : aA;
            const uint32_t* b = (ks & 1) ? bB : bA;
            #pragma unroll
            for (int t = 0; t < 2; ++t)
                #pragma unroll
                for (int u = 0; u < 8; ++u)
                    mma16(c[t][u], a + t * 4, b + u * 2);
        }
    }
}

__device__ __forceinline__ void zero_c(float c[2][8][4]) {
    #pragma unroll
    for (int t = 0; t < 2; ++t)
        #pragma unroll
        for (int u = 0; u < 8; ++u)
            #pragma unroll
            for (int j = 0; j < 4; ++j) c[t][u][j] = 0.0f;
}

// fp32 row-major epilogue (final output).
__device__ __forceinline__ void epi_store_f(float c[2][8][4], float* __restrict__ C,
                                            long ldc) {
    const int tid = threadIdx.x, wid = tid >> 5, lane = tid & 31;
    const int warpM = wid & 3, warpN = wid >> 2;
    const int lr = lane >> 2, lc = lane & 3;
    #pragma unroll
    for (int t = 0; t < 2; ++t)
        #pragma unroll
        for (int u = 0; u < 8; ++u) {
            const int r = warpM * 32 + t * 16 + lr;
            const int n = warpN * 64 + u * 8 + lc * 2;
            *(float2*)&C[(size_t)r * ldc + n]       = make_float2(c[t][u][0], c[t][u][1]);
            *(float2*)&C[(size_t)(r + 8) * ldc + n] = make_float2(c[t][u][2], c[t][u][3]);
        }
}

// fp16 row-major epilogue (T, scores).
__device__ __forceinline__ void epi_store_h(float c[2][8][4], __half* __restrict__ C,
                                            long ldc) {
    const int tid = threadIdx.x, wid = tid >> 5, lane = tid & 31;
    const int warpM = wid & 3, warpN = wid >> 2;
    const int lr = lane >> 2, lc = lane & 3;
    #pragma unroll
    for (int t = 0; t < 2; ++t)
        #pragma unroll
        for (int u = 0; u < 8; ++u) {
            const int r = warpM * 32 + t * 16 + lr;
            const int n = warpN * 64 + u * 8 + lc * 2;
            *(__half2*)&C[(size_t)r * ldc + n]       = __floats2half2_rn(c[t][u][0], c[t][u][1]);
            *(__half2*)&C[(size_t)(r + 8) * ldc + n] = __floats2half2_rn(c[t][u][2], c[t][u][3]);
        }
}

// fp16 transposed epilogue with scale: Ct[n][m] (for V^T and M^T).
__device__ __forceinline__ void epi_store_T(float c[2][8][4], __half* __restrict__ Ct,
                                            long ldm, float scl) {
    const int tid = threadIdx.x, wid = tid >> 5, lane = tid & 31;
    const int warpM = wid & 3, warpN = wid >> 2;
    const int lr = lane >> 2, lc = lane & 3;
    #pragma unroll
    for (int t = 0; t < 2; ++t)
        #pragma unroll
        for (int u = 0; u < 8; ++u) {
            const int r = warpM * 32 + t * 16 + lr;
            const int n = warpN * 64 + u * 8 + lc * 2;
            Ct[(size_t)n * ldm + r]           = __float2half_rn(c[t][u][0] * scl);
            Ct[(size_t)(n + 1) * ldm + r]     = __float2half_rn(c[t][u][1] * scl);
            Ct[(size_t)n * ldm + r + 8]       = __float2half_rn(c[t][u][2] * scl);
            Ct[(size_t)(n + 1) * ldm + r + 8] = __float2half_rn(c[t][u][3] * scl);
        }
}

// ---------------------------------------------------------------------------
// Spin helpers (producer/consumer across blocks within one kernel).
// ---------------------------------------------------------------------------
__device__ __forceinline__ void signal_done(int* cnt) {
    __threadfence();
    __syncthreads();
    if (threadIdx.x == 0) atomicAdd(cnt, 1);
}

__device__ __forceinline__ void wait_for(const int* cnt, int target) {
    if (threadIdx.x == 0) {
        while (*(volatile const int*)cnt < target) __nanosleep(64);
        __threadfence();
    }
    __syncthreads();
}

// ---------------------------------------------------------------------------
// Fused prepass: ids [0,4096): round x -> fp16.
//                [4096,5120): round Wq/Wk -> fp16 (layout preserved).
//                [5120,6144): transpose+round Wv -> slot 2.
// Block 0 also resets the dataflow counters for this run.
// ---------------------------------------------------------------------------
__global__ __launch_bounds__(256) void prepass_kernel(const float* __restrict__ x,
                                                      const float* __restrict__ Wq,
                                                      const float* __restrict__ Wk,
                                                      const float* __restrict__ Wv) {
    const int id = blockIdx.x;
    if (id == 0) {
        if (threadIdx.x == 0) g_mcnt = 0;
        if (threadIdx.x < 64) {
            g_tcnt[threadIdx.x] = 0;
            g_scnt[threadIdx.x] = 0;
            g_smcnt[threadIdx.x] = 0;
        }
        if (threadIdx.x < 32) g_vcnt[threadIdx.x] = 0;
    }
    if (id < 5120) {
        const float* __restrict__ src;
        __half* __restrict__ dst;
        size_t i;
        if (id < 4096) {
            src = x; dst = g_xh;
            i = (size_t)id * 256 + threadIdx.x;
        } else {
            const int z = (id - 4096) >> 9;
            src = z ? Wk : Wq;
            dst = g_wh + (size_t)z * DM * DM;
            i = (size_t)((id - 4096) & 511) * 256 + threadIdx.x;
        }
        const float4 a = ((const float4*)src)[2 * i];
        const float4 b = ((const float4*)src)[2 * i + 1];
        __half2 h[4] = { __floats2half2_rn(a.x, a.y), __floats2half2_rn(a.z, a.w),
                         __floats2half2_rn(b.x, b.y), __floats2half2_rn(b.z, b.w) };
        ((uint4*)dst)[i] = *(const uint4*)h;
    } else {
        __shared__ float t[32][33];
        __half* __restrict__ O = g_wh + (size_t)2 * DM * DM;
        const int r = id - 5120;
        const int tx = threadIdx.x & 31, ty = threadIdx.x >> 5;
        const int n = (r & 31) * 32 + tx;
        const int k0 = (r >> 5) * 32;
        for (int i = ty; i < 32; i += 8) t[i][tx] = Wv[(size_t)(k0 + i) * DM + n];
        __syncthreads();
        const int ko = (r >> 5) * 32 + tx;
        const int n0 = (r & 31) * 32;
        for (int i = ty; i < 32; i += 8)
            O[(size_t)(n0 + i) * DM + ko] = __float2half_rn(t[tx][i]);
    }
}

// ---------------------------------------------------------------------------
// MEGA kernel: full dataflow over block-id ranges (one launch).
//   [0,64):      M = (Wq Wk^T)/32 -> M^T         (signals mcnt)
//   [64,576):    T = x M (waits mcnt==64)        (signals tcnt[mb])
//   [576,1088):  V-projection -> V^T             (signals vcnt[b*8+n])
//   [1088,1632): S = T x^T triangular (waits tcnt[gb]==8) (signals scnt[gb])
//   [1632,2144): softmax, 16 rows/block (waits scnt[gb]==by+1) (signals smcnt)
//   [2144,2656): O = P V (waits smcnt[gb]==8 && vcnt==16), heavy-first
// ---------------------------------------------------------------------------
__global__ __launch_bounds__(256, 2) void mega_kernel(float* __restrict__ out) {
    extern __shared__ __half smh[];
    const int id = blockIdx.x;

    if (id < 1088 || (id >= 1088 && id < 1632) || id >= 2144) {
        // GEMM-shaped block
        float c[2][8][4];
        zero_c(c);

        if (id < 64) {
            const long m0 = (long)(id >> 3) * BM;   // Wq row (d_in_q)
            const long n0 = (long)(id & 7) * BN;    // Wk row (d_in_k)
            const __half* A = g_wh + (size_t)m0 * DM;                    // Wq
            const __half* B = g_wh + (size_t)DM * DM + (size_t)n0 * DM;  // Wk

            gemm_h(smh, A, DM, B, DM, DM / BK, c);

            epi_store_T(c, g_mth + (size_t)n0 * DM + m0, DM, SCALE);
            signal_done(&g_mcnt);
        } else if (id < 576) {
            const int r = id - 64;
            const long m0 = (long)(r >> 3) * BM;
            const long n0 = (long)(r & 7) * BN;

            wait_for(&g_mcnt, 64);

            const __half* A = g_xh + (size_t)m0 * DM;
            const __half* B = g_mth + (size_t)n0 * DM;

            gemm_h(smh, A, DM, B, DM, DM / BK, c);

            epi_store_h(c, g_th + (size_t)m0 * DM + n0, DM);
            signal_done(&g_tcnt[r >> 3]);
        } else if (id < 1088) {
            const int r = id - 576;
            const long n0 = (long)(r & 7) * BN;
            const long m0 = (long)(r >> 3) * BM;
            const __half* A = g_xh + (size_t)m0 * DM;
            const __half* B = g_wh + (size_t)2 * DM * DM + (size_t)n0 * DM;

            gemm_h(smh, A, DM, B, DM, DM / BK, c);

            const int b = (int)(m0 / SEQ);
            const long mloc = m0 - (long)b * SEQ;
            __half* Ct = g_vth + ((size_t)b * DM + n0) * SEQ + mloc;
            epi_store_T(c, Ct, SEQ, 1.0f);
            signal_done(&g_vcnt[b * 8 + (r & 7)]);
        } else if (id < 1632) {
            const int sid = id - 1088;
            const int b = sid / 136;
            const int tt = sid - b * 136;
            int by = (int)((sqrtf(8.0f * tt + 1.0f) - 1.0f) * 0.5f);
            while ((by + 1) * (by + 2) / 2 <= tt) ++by;
            while (by * (by + 1) / 2 > tt) --by;
            const int bx = tt - by * (by + 1) / 2;

            const long m0 = (long)by * BM;
            const long n0 = (long)bx * BN;
            const int gb = b * 16 + by;

            wait_for(&g_tcnt[gb], 8);

            const __half* A = g_th + ((size_t)b * SEQ + m0) * DM;
            const __half* B = g_xh + ((size_t)b * SEQ + n0) * DM;

            gemm_h(smh, A, DM, B, DM, DM / BK, c);

            __half* C = g_ph + ((size_t)b * SEQ + m0) * SEQ + n0;
            epi_store_h(c, C, SEQ);
            signal_done(&g_scnt[gb]);
        } else {
            // PV: heavy-first by m-level
            const int pid = id - 2144;
            const int by = 15 - (pid >> 5);
            const int rest = pid & 31;
            const int b = rest >> 3;
            const int n0t = rest & 7;
            const int gb = b * 16 + by;

            wait_for(&g_smcnt[gb], 8);
            wait_for(&g_vcnt[b * 8 + n0t], 16);

            const long m0 = (long)by * BM;
            const long n0 = (long)n0t * BN;
            const __half* A = g_ph + ((size_t)b * SEQ + m0) * SEQ;
            const __half* B = g_vth + ((size_t)b * DM + n0) * SEQ;
            const int nchunks = 2 * (by + 1);

            gemm_h(smh, A, SEQ, B, SEQ, nchunks, c);

            float* C = out + ((size_t)b * SEQ + m0) * DM + n0;
            epi_store_f(c, C, DM);
        }
    } else {
        // Softmax range [1632,2144): 16 rows per block, row kept in registers.
        __shared__ float red[8];
        const int sid = id - 1632;
        const int gb = sid >> 3;
        const int sub = sid & 7;
        const int b = gb >> 4;
        const int by = gb & 15;
        const int nzero = (by + 1) << 7;
        const int tid = threadIdx.x, wid = tid >> 5, lane = tid & 31;

        wait_for(&g_scnt[gb], by + 1);

        __half* __restrict__ Pbase = g_ph + (size_t)b * SEQ * SEQ;

        for (int rr = 0; rr < 16; ++rr) {
            const int qb = by * 128 + sub * 16 + rr;   // row within batch
            __half* __restrict__ P = Pbase + (size_t)qb * SEQ;
            const int nvalid = qb + 1;

            float v[8];
            float lmax = -CUDART_INF_F;
            #pragma unroll
            for (int j = 0; j < 8; ++j) {
                const int col = j * 256 + tid;
                if (col < nvalid) {
                    v[j] = __half2float(P[col]);
                    lmax = fmaxf(lmax, v[j]);
                }
            }
            #pragma unroll
            for (int o = 16; o > 0; o >>= 1)
                lmax = fmaxf(lmax, __shfl_xor_sync(0xFFFFFFFFu, lmax, o));
            if (lane == 0) red[wid] = lmax;
            __syncthreads();
            float rmax = red[0];
            #pragma unroll
            for (int w = 1; w < 8; ++w) rmax = fmaxf(rmax, red[w]);
            __syncthreads();

            float lsum = 0.0f;
            #pragma unroll
            for (int j = 0; j < 8; ++j) {
                const int col = j * 256 + tid;
                if (col < nvalid) {
                    v[j] = __expf(v[j] - rmax);
                    lsum += v[j];
                }
            }
            #pragma unroll
            for (int o = 16; o > 0; o >>= 1)
                lsum += __shfl_xor_sync(0xFFFFFFFFu, lsum, o);
            if (lane == 0) red[wid] = lsum;
            __syncthreads();
            float rsum = red[0];
            #pragma unroll
            for (int w = 1; w < 8; ++w) rsum += red[w];
            const float inv = 1.0f / rsum;

            #pragma unroll
            for (int j = 0; j < 8; ++j) {
                const int col = j * 256 + tid;
                if (col < nzero)
                    P[col] = __float2half_rn((col < nvalid) ? v[j] * inv : 0.0f);
            }
            __syncthreads();   // protect red[] before next row
        }
        signal_done(&g_smcnt[gb]);
    }
}

// ---------------------------------------------------------------------------
extern "C" void kernel_launch(void* const* d_in, const int* in_sizes, int n_in,
                              void* d_out, int out_size) {
    (void)in_sizes; (void)n_in; (void)out_size;
    const float* x  = (const float*)d_in[0];
    const float* Wq = (const float*)d_in[1];
    const float* Wk = (const float*)d_in[2];
    const float* Wv = (const float*)d_in[3];
    float* out = (float*)d_out;

    cudaFuncSetAttribute(mega_kernel, cudaFuncAttributeMaxDynamicSharedMemorySize, SMEM_BYTES);

    prepass_kernel<<<6144, 256>>>(x, Wq, Wk, Wv);
    mega_kernel<<<2656, 256, SMEM_BYTES>>>(out);     // M->T->S->softmax->PV, V fills tails
}